// round 1
// baseline (speedup 1.0000x reference)
#include <cuda_runtime.h>
#include <cstdint>

#define F 128
#define NMAX 50176

// ---------------- device scratch (no allocs allowed) ----------------
__device__ int   g_is64;
__device__ float g_W[F * F];             // evolved GCN weight [k][j]
__device__ float g_wT[4 * F * F];        // w_ih transposed: [k][j], j in [0,4F)
__device__ float g_dis[NMAX];            // D^{-1/2}
__device__ int   g_deg[NMAX];
__device__ float g_hagg[(size_t)NMAX * F];  // aggregated messages (pre-transform)

// ---------------- dtype sniffer: int64 vs int32 edge_index ----------------
__global__ void detect_kernel(const int* ei) {
    if (blockIdx.x == 0 && threadIdx.x == 0) {
        int z = 1;
        #pragma unroll
        for (int j = 1; j < 64; j += 2)
            if (ei[j] != 0) z = 0;
        g_is64 = z;
    }
}

// ---------------- zero scratch ----------------
__global__ void zero_kernel(int n) {
    int idx = blockIdx.x * blockDim.x + threadIdx.x;
    int stride = gridDim.x * blockDim.x;
    int tot4 = n * (F / 4);
    float4 z4 = make_float4(0.f, 0.f, 0.f, 0.f);
    for (int i = idx; i < tot4; i += stride)
        reinterpret_cast<float4*>(g_hagg)[i] = z4;
    for (int i = idx; i < n; i += stride)
        g_deg[i] = 0;
}

// ---------------- in-degree ----------------
__global__ void deg_kernel(const void* __restrict__ ei, int E) {
    int e = blockIdx.x * blockDim.x + threadIdx.x;
    if (e >= E) return;
    int dst;
    if (g_is64) dst = (int)reinterpret_cast<const long long*>(ei)[(size_t)E + e];
    else        dst = reinterpret_cast<const int*>(ei)[(size_t)E + e];
    atomicAdd(&g_deg[dst], 1);
}

// ---------------- dis = (deg_in + 1)^{-1/2}  (self-loop included) ----------------
__global__ void dis_kernel(int n) {
    int v = blockIdx.x * blockDim.x + threadIdx.x;
    if (v < n) g_dis[v] = rsqrtf((float)(g_deg[v] + 1));
}

// ---------------- transpose w_ih [4F,F] -> [F,4F] ----------------
__global__ void transpose_kernel(const float* __restrict__ w_ih) {
    int id = blockIdx.x * blockDim.x + threadIdx.x;
    if (id < 4 * F * F) {
        int j = id / F, k = id % F;
        g_wT[k * (4 * F) + j] = w_ih[id];
    }
}

// ---------------- LSTM one-step weight evolution ----------------
__global__ void evolve_kernel(const float* __restrict__ W0,
                              const float* __restrict__ b_ih,
                              const float* __restrict__ b_hh) {
    __shared__ float sRow[F];
    int r = blockIdx.x, c = threadIdx.x;
    sRow[c] = W0[r * F + c];
    __syncthreads();
    float ai = 0.f, ag = 0.f, ao = 0.f;
    #pragma unroll 8
    for (int k = 0; k < F; k++) {
        float w = sRow[k];
        const float* base = &g_wT[k * (4 * F)];
        ai = fmaf(w, base[c],          ai);   // i gate (cols 0..F)
        ag = fmaf(w, base[c + 2 * F],  ag);   // g gate (cols 2F..3F)
        ao = fmaf(w, base[c + 3 * F],  ao);   // o gate (cols 3F..4F)
    }
    ai += b_ih[c]         + b_hh[c];
    ag += b_ih[c + 2 * F] + b_hh[c + 2 * F];
    ao += b_ih[c + 3 * F] + b_hh[c + 3 * F];
    float si = 1.f / (1.f + expf(-ai));
    float so = 1.f / (1.f + expf(-ao));
    float cc = si * tanhf(ag);
    g_W[r * F + c] = so * tanhf(cc);
}

// ---------------- edge aggregation: h_agg[dst] += dis[src]*dis[dst] * x[src] ----------------
// one warp per edge, one float4 per lane, vector red.global
__global__ void agg_kernel(const float* __restrict__ x, const void* __restrict__ ei, int E) {
    int gw = blockIdx.x * 8 + (threadIdx.x >> 5);
    if (gw >= E) return;
    int lane = threadIdx.x & 31;
    int src, dst;
    if (g_is64) {
        const long long* p = reinterpret_cast<const long long*>(ei);
        src = (int)p[gw]; dst = (int)p[(size_t)E + gw];
    } else {
        const int* p = reinterpret_cast<const int*>(ei);
        src = p[gw]; dst = p[(size_t)E + gw];
    }
    float coef = g_dis[src] * g_dis[dst];
    float4 v = __ldg(reinterpret_cast<const float4*>(x + (size_t)src * F) + lane);
    v.x *= coef; v.y *= coef; v.z *= coef; v.w *= coef;
    float* dp = g_hagg + (size_t)dst * F + lane * 4;
    asm volatile("red.global.add.v4.f32 [%0], {%1,%2,%3,%4};"
                 :: "l"(dp), "f"(v.x), "f"(v.y), "f"(v.z), "f"(v.w) : "memory");
}

// ---------------- fused: (h_agg + dis^2*x) @ W + b -> relu -> @ Wc^T + bc ----------------
// 256 threads (8 warps), 8 rows per warp, W + Wc + bias + staged inputs in smem.
__global__ void final_kernel(const float* __restrict__ x,
                             const float* __restrict__ gcn_bias,
                             const float* __restrict__ Wc,
                             const float* __restrict__ bc,
                             float* __restrict__ out, int n) {
    extern __shared__ float sm[];
    float* sW  = sm;                   // F*F
    float* sWc = sW + F * F;           // 2*F
    float* sB  = sWc + 2 * F;          // F
    float* sIn = sB + F;               // 64*F

    int tid = threadIdx.x;
    for (int i = tid; i < (F * F) / 4; i += blockDim.x)
        reinterpret_cast<float4*>(sW)[i] = reinterpret_cast<const float4*>(g_W)[i];
    if (tid < (2 * F) / 4)
        reinterpret_cast<float4*>(sWc)[tid] = __ldg(reinterpret_cast<const float4*>(Wc) + tid);
    if (tid < F / 4)
        reinterpret_cast<float4*>(sB)[tid] = __ldg(reinterpret_cast<const float4*>(gcn_bias) + tid);
    __syncthreads();

    int warp = tid >> 5, lane = tid & 31;
    int rowBase = blockIdx.x * 64 + warp * 8;

    // stage 8 input rows: in = h_agg[v] + dis[v]^2 * x[v]  (self-loop folded in)
    #pragma unroll
    for (int r = 0; r < 8; r++) {
        int v = rowBase + r;
        float4 val = make_float4(0.f, 0.f, 0.f, 0.f);
        if (v < n) {
            float d = g_dis[v];
            float d2 = d * d;
            float4 hv = reinterpret_cast<const float4*>(g_hagg + (size_t)v * F)[lane];
            float4 xv = __ldg(reinterpret_cast<const float4*>(x + (size_t)v * F) + lane);
            val.x = fmaf(d2, xv.x, hv.x);
            val.y = fmaf(d2, xv.y, hv.y);
            val.z = fmaf(d2, xv.z, hv.z);
            val.w = fmaf(d2, xv.w, hv.w);
        }
        reinterpret_cast<float4*>(&sIn[(warp * 8 + r) * F])[lane] = val;
    }
    __syncwarp();

    float acc[8][4];
    #pragma unroll
    for (int r = 0; r < 8; r++) {
        acc[r][0] = 0.f; acc[r][1] = 0.f; acc[r][2] = 0.f; acc[r][3] = 0.f;
    }

    #pragma unroll 4
    for (int k = 0; k < F; k++) {
        float4 w = *reinterpret_cast<const float4*>(&sW[k * F + lane * 4]);
        #pragma unroll
        for (int r = 0; r < 8; r++) {
            float in = sIn[(warp * 8 + r) * F + k];
            acc[r][0] = fmaf(in, w.x, acc[r][0]);
            acc[r][1] = fmaf(in, w.y, acc[r][1]);
            acc[r][2] = fmaf(in, w.z, acc[r][2]);
            acc[r][3] = fmaf(in, w.w, acc[r][3]);
        }
    }

    float b0 = sB[lane * 4], b1 = sB[lane * 4 + 1], b2 = sB[lane * 4 + 2], b3 = sB[lane * 4 + 3];
    float c00 = sWc[lane * 4],     c01 = sWc[lane * 4 + 1],
          c02 = sWc[lane * 4 + 2], c03 = sWc[lane * 4 + 3];
    float c10 = sWc[F + lane * 4],     c11 = sWc[F + lane * 4 + 1],
          c12 = sWc[F + lane * 4 + 2], c13 = sWc[F + lane * 4 + 3];
    float obc0 = __ldg(bc), obc1 = __ldg(bc + 1);

    #pragma unroll
    for (int r = 0; r < 8; r++) {
        float t0 = fmaxf(acc[r][0] + b0, 0.f);
        float t1 = fmaxf(acc[r][1] + b1, 0.f);
        float t2 = fmaxf(acc[r][2] + b2, 0.f);
        float t3 = fmaxf(acc[r][3] + b3, 0.f);
        float p0 = t0 * c00 + t1 * c01 + t2 * c02 + t3 * c03;
        float p1 = t0 * c10 + t1 * c11 + t2 * c12 + t3 * c13;
        #pragma unroll
        for (int off = 16; off > 0; off >>= 1) {
            p0 += __shfl_down_sync(0xffffffffu, p0, off);
            p1 += __shfl_down_sync(0xffffffffu, p1, off);
        }
        int v = rowBase + r;
        if (lane == 0 && v < n) {
            out[2 * v]     = p0 + obc0;
            out[2 * v + 1] = p1 + obc1;
        }
    }
}

// ---------------- launch ----------------
extern "C" void kernel_launch(void* const* d_in, const int* in_sizes, int n_in,
                              void* d_out, int out_size) {
    const float* x        = (const float*)d_in[0];
    const float* W0       = (const float*)d_in[1];
    const float* w_ih     = (const float*)d_in[2];
    // d_in[3] = w_hh (unused: h0 = 0)
    const float* b_ih     = (const float*)d_in[4];
    const float* b_hh     = (const float*)d_in[5];
    const float* gcn_bias = (const float*)d_in[6];
    const float* Wc       = (const float*)d_in[7];
    const float* bc       = (const float*)d_in[8];
    const void*  ei       = d_in[9];

    int n = in_sizes[0] / F;
    int E = in_sizes[9] / 2;
    float* out = (float*)d_out;

    detect_kernel<<<1, 32>>>((const int*)ei);
    zero_kernel<<<512, 256>>>(n);
    deg_kernel<<<(E + 255) / 256, 256>>>(ei, E);
    dis_kernel<<<(n + 255) / 256, 256>>>(n);
    transpose_kernel<<<(4 * F * F + 255) / 256, 256>>>(w_ih);
    evolve_kernel<<<F, F>>>(W0, b_ih, b_hh);
    agg_kernel<<<(E + 7) / 8, 256>>>(x, ei, E);

    size_t smemBytes = (size_t)(F * F + 2 * F + F + 64 * F) * sizeof(float);
    cudaFuncSetAttribute(final_kernel, cudaFuncAttributeMaxDynamicSharedMemorySize, (int)smemBytes);
    final_kernel<<<(n + 63) / 64, 256, smemBytes>>>(x, gcn_bias, Wc, bc, out, n);
}